// round 3
// baseline (speedup 1.0000x reference)
#include <cuda_runtime.h>

// FullNet_29008209117719: tau[N,48,9] = a[n,j] * T[ch,j]
//   T[ch,j] = exp(w_lin[j,ch]) * (j<2 ? 1 : FILT[j-2,ch])   (constant per launch)
//   a[n,0]=c[n,0]; a[n,1]=c[n,1]; a[n,2+g]=c[n,2+g]*sigmoid(MLP_g(t_p[n]))
// Store-bound: 453 MB output. One fused kernel, coalesced float4 stores.

#define NTH 256
#define NS  256           // samples per block
#define ROW 432           // 48 channels * 9 species
#define NF4 (ROW / 4)     // 108 float4 per sample row
#define NW  497           // total weight floats staged in smem

__device__ __constant__ unsigned char d_F16[7][16] = {
    {1,1,1,1,1,1,1,1,1,1,1,1,1,0,1,1},  // h2o
    {0,0,0,1,1,0,1,1,0,0,0,0,1,0,0,0},  // o3
    {0,0,1,1,1,1,1,1,0,0,0,1,1,1,1,0},  // co2
    {1,0,0,0,0,0,0,0,0,0,1,0,0,0,0,0},  // o2
    {0,0,1,0,0,0,0,1,1,0,0,0,1,0,1,0},  // n2o
    {0,0,0,0,0,0,0,0,1,0,0,0,0,0,0,1},  // ch4
    {0,0,0,0,0,0,0,1,0,0,0,0,1,0,0,0},  // co
};

// smem weight layout offsets
#define OFF_W1 0      // 7*6*2 = 84
#define OFF_B1 84     // 7*6   = 42
#define OFF_W2 126    // 7*4*6 = 168
#define OFF_B2 294    // 7*4   = 28
#define OFF_W3 322    // 7*4*4 = 112
#define OFF_B3 434    // 7*4   = 28
#define OFF_WO 462    // 7*4   = 28
#define OFF_BO 490    // 7     = 7   -> 497 total

__global__ __launch_bounds__(NTH) void fullnet_kernel(
    const float* __restrict__ t_p,   // [N,2]
    const float* __restrict__ c,     // [N,9]
    const float* __restrict__ w_lin, // [9,48]
    const float* __restrict__ W1, const float* __restrict__ b1,
    const float* __restrict__ W2, const float* __restrict__ b2,
    const float* __restrict__ W3, const float* __restrict__ b3,
    const float* __restrict__ Wo, const float* __restrict__ bo,
    float* __restrict__ out,         // [N,48,9]
    int Ntot)
{
    __shared__ float sT[ROW];        // T[ch*9+j]
    __shared__ float sa[NS][9];      // per-sample scalars
    __shared__ float sw[NW];         // all MLP weights

    const int tid = threadIdx.x;

    // ---- stage weights into smem ----
    for (int i = tid; i < NW; i += NTH) {
        float v;
        if      (i < OFF_B1) v = W1[i - OFF_W1];
        else if (i < OFF_W2) v = b1[i - OFF_B1];
        else if (i < OFF_B2) v = W2[i - OFF_W2];
        else if (i < OFF_W3) v = b2[i - OFF_B2];
        else if (i < OFF_B3) v = W3[i - OFF_W3];
        else if (i < OFF_WO) v = b3[i - OFF_B3];
        else if (i < OFF_BO) v = Wo[i - OFF_WO];
        else                 v = bo[i - OFF_BO];
        sw[i] = v;
    }

    // ---- build constant table T ----
    for (int k = tid; k < ROW; k += NTH) {
        int ch = k / 9, j = k % 9;
        float m = (j < 2) ? 1.0f : (float)d_F16[j - 2][ch / 3];
        sT[k] = m * expf(w_lin[j * 48 + ch]);
    }

    // ---- per-sample loads + MLPs ----
    const int n = blockIdx.x * NS + tid;
    float tt = 0.f, pp = 0.f;
    float cv[9];
    if (n < Ntot) {
        tt = t_p[2 * n];
        pp = t_p[2 * n + 1];
        #pragma unroll
        for (int j = 0; j < 9; j++) cv[j] = c[9 * n + j];
    } else {
        #pragma unroll
        for (int j = 0; j < 9; j++) cv[j] = 0.f;
    }

    __syncthreads();  // weights staged

    sa[tid][0] = cv[0];
    sa[tid][1] = cv[1];

    #pragma unroll 1
    for (int g = 0; g < 7; g++) {
        const float* w1 = &sw[OFF_W1 + g * 12];
        const float* B1 = &sw[OFF_B1 + g * 6];
        float h1[6];
        #pragma unroll
        for (int h = 0; h < 6; h++) {
            float v = fmaf(w1[2 * h], tt, fmaf(w1[2 * h + 1], pp, B1[h]));
            h1[h] = v > 0.f ? v : 0.f;
        }
        const float* w2 = &sw[OFF_W2 + g * 24];
        const float* B2 = &sw[OFF_B2 + g * 4];
        float h2[4];
        #pragma unroll
        for (int o = 0; o < 4; o++) {
            float v = B2[o];
            #pragma unroll
            for (int h = 0; h < 6; h++) v = fmaf(w2[o * 6 + h], h1[h], v);
            h2[o] = v > 0.f ? v : 0.f;
        }
        const float* w3 = &sw[OFF_W3 + g * 16];
        const float* B3 = &sw[OFF_B3 + g * 4];
        float h3[4];
        #pragma unroll
        for (int o = 0; o < 4; o++) {
            float v = B3[o];
            #pragma unroll
            for (int h = 0; h < 4; h++) v = fmaf(w3[o * 4 + h], h2[h], v);
            h3[o] = v > 0.f ? v : 0.f;
        }
        float v = sw[OFF_BO + g];
        #pragma unroll
        for (int h = 0; h < 4; h++) v = fmaf(sw[OFF_WO + g * 4 + h], h3[h], v);
        float ke = 1.0f / (1.0f + __expf(-v));
        sa[tid][2 + g] = cv[2 + g] * ke;
    }

    __syncthreads();  // sa + sT ready

    // ---- cooperative coalesced write of the [NS,432] tile ----
    float* outb = out + (size_t)blockIdx.x * NS * ROW;
    const int base_n = blockIdx.x * NS;
    for (int i = tid; i < NS * NF4; i += NTH) {
        int nl = i / NF4;
        if (base_n + nl >= Ntot) break;
        int k = (i - nl * NF4) * 4;       // element index within the 432-row
        float4 t4 = *(const float4*)&sT[k];
        int j = k % 9;
        float4 r;
        r.x = sa[nl][j] * t4.x; if (++j == 9) j = 0;
        r.y = sa[nl][j] * t4.y; if (++j == 9) j = 0;
        r.z = sa[nl][j] * t4.z; if (++j == 9) j = 0;
        r.w = sa[nl][j] * t4.w;
        *(float4*)&outb[(size_t)nl * ROW + k] = r;
    }
}

extern "C" void kernel_launch(void* const* d_in, const int* in_sizes, int n_in,
                              void* d_out, int out_size)
{
    const float* t_p   = (const float*)d_in[0];
    const float* c     = (const float*)d_in[1];
    const float* w_lin = (const float*)d_in[2];
    const float* W1    = (const float*)d_in[3];
    const float* b1    = (const float*)d_in[4];
    const float* W2    = (const float*)d_in[5];
    const float* b2    = (const float*)d_in[6];
    const float* W3    = (const float*)d_in[7];
    const float* b3    = (const float*)d_in[8];
    const float* Wo    = (const float*)d_in[9];
    const float* bo    = (const float*)d_in[10];
    float* out = (float*)d_out;

    int Ntot = in_sizes[1] / 9;   // c is [N,9]
    int nblk = (Ntot + NS - 1) / NS;
    fullnet_kernel<<<nblk, NTH>>>(t_p, c, w_lin, W1, b1, W2, b2, W3, b3, Wo, bo,
                                  out, Ntot);
}